// round 15
// baseline (speedup 1.0000x reference)
#include <cuda_runtime.h>
#include <cuda_bf16.h>
#include <cuda_fp16.h>
#include <cstdint>

#define N_ 20000
#define E_ 8000
#define F_ 64
#define EPS 1e-10f

#define NPAD 20032          // N_ padded to multiple of 64
#define TK 64               // K elements per chunk
#define NCH1 313            // NPAD/64
#define SPLIT1 7
#define CPS1 45             // ceil(313/7)
#define ETILES1 63          // ceil(E_/128)
#define NCH2 125            // E_/64
#define SPLIT2 3
#define CPS2 42             // ceil(125/3)
#define NTILES2 157         // ceil(N_/128)

// gemm1 per-stage: P 8K (XsT fp16) | Q 16K (H fp16, two 8K e-halves)
#define G1_P0 0
#define G1_Q0 8192
// gemm2 per-stage: A 16K (H fp16) | B 8K (YdT fp16)
#define G2_A0 0
#define G2_B0 16384
#define STAGE 24576
#define NSTG 3
#define G_TOTAL (NSTG * STAGE)   // 73728 -> 3 CTAs/SM (216KB smem)

// ---------------- scratch ----------------
__device__ float g_dv[N_];
__device__ float g_de[E_];
__device__ float g_YT[64 * E_];                      // Y^T [f][e]
__device__ __align__(16) unsigned short g_H16[(size_t)N_ * E_];  // H fp16
__device__ __align__(16) unsigned short g_XsTf[64 * NPAD];       // fp16
__device__ __align__(16) unsigned short g_YdTf[64 * E_];         // fp16 [f][e]

// ---------------- helpers ----------------
__device__ __forceinline__ uint32_t smem_u32(const void* p) {
    uint32_t a;
    asm("{ .reg .u64 tmp; cvta.to.shared.u64 tmp, %1; cvt.u32.u64 %0, tmp; }"
        : "=r"(a) : "l"(p));
    return a;
}
#define SW128(o) ((uint32_t)(o) ^ (((uint32_t)(o) >> 3) & 0x70))

__device__ __forceinline__ uint2 cvt_h4(float4 v) {
    __half2 a = __floats2half2_rn(v.x, v.y);
    __half2 b = __floats2half2_rn(v.z, v.w);
    return make_uint2(*(uint32_t*)&a, *(uint32_t*)&b);
}

#define LDMX4(r, addr) \
    asm volatile("ldmatrix.sync.aligned.m8n8.x4.shared.b16 {%0,%1,%2,%3}, [%4];" \
        : "=r"((r)[0]), "=r"((r)[1]), "=r"((r)[2]), "=r"((r)[3]) : "r"(addr))
#define LDMX4T(r, addr) \
    asm volatile("ldmatrix.sync.aligned.m8n8.x4.trans.shared.b16 {%0,%1,%2,%3}, [%4];" \
        : "=r"((r)[0]), "=r"((r)[1]), "=r"((r)[2]), "=r"((r)[3]) : "r"(addr))

__device__ __forceinline__ void mma_f16(float* c, const uint32_t* a,
                                        uint32_t b0, uint32_t b1) {
    asm volatile(
        "mma.sync.aligned.m16n8k16.row.col.f32.f16.f16.f32 "
        "{%0,%1,%2,%3}, {%4,%5,%6,%7}, {%8,%9}, {%0,%1,%2,%3};"
        : "+f"(c[0]), "+f"(c[1]), "+f"(c[2]), "+f"(c[3])
        : "r"(a[0]), "r"(a[1]), "r"(a[2]), "r"(a[3]), "r"(b0), "r"(b1));
}

__device__ __forceinline__ void cp_async16(uint32_t dst, const void* src) {
    asm volatile("cp.async.cg.shared.global [%0], [%1], 16;"
                 :: "r"(dst), "l"(src) : "memory");
}
__device__ __forceinline__ void cp_async16z(uint32_t dst, const void* src, int srcsz) {
    asm volatile("cp.async.cg.shared.global [%0], [%1], 16, %2;"
                 :: "r"(dst), "l"(src), "r"(srcsz) : "memory");
}
#define CP_COMMIT() asm volatile("cp.async.commit_group;" ::: "memory")
#define CP_WAIT1()  asm volatile("cp.async.wait_group 1;" ::: "memory")
#define CP_WAIT0()  asm volatile("cp.async.wait_group 0;" ::: "memory")

// ---------------- zero scratch (incl. output + g_dv) ----------------
__global__ void zero_scratch(float* __restrict__ Z) {
    int i = blockIdx.x * blockDim.x + threadIdx.x;
    if (i < N_ * F_) Z[i] = 0.0f;
    if (i < 64 * E_) g_YT[i] = 0.0f;
    if (i < E_) g_de[i] = 0.0f;
    if (i < N_) g_dv[i] = 0.0f;
}

// ---------------- degrees + H16 conversion (one pass, no barriers) ----------
__global__ void __launch_bounds__(256) degrees_kernel(const float* __restrict__ H) {
    const int t = threadIdx.x;
    const int lane = t & 31;
    const int r0 = blockIdx.x * 46;
    const int r1 = (r0 + 46 < N_) ? r0 + 46 : N_;

    float de_acc[8][4];
#pragma unroll
    for (int j = 0; j < 8; j++)
#pragma unroll
        for (int q = 0; q < 4; q++) de_acc[j][q] = 0.0f;

    for (int r = r0; r < r1; r++) {
        const float* __restrict__ row = H + (size_t)r * E_;
        unsigned short* __restrict__ hrow = g_H16 + (size_t)r * E_;
        float rs = 0.0f;
#pragma unroll
        for (int j = 0; j < 8; j++) {
            int c4 = (j * 256 + t) * 4;
            if (c4 < E_) {
                float4 v = *(const float4*)(row + c4);
                rs += (v.x + v.y) + (v.z + v.w);
                de_acc[j][0] += v.x;
                de_acc[j][1] += v.y;
                de_acc[j][2] += v.z;
                de_acc[j][3] += v.w;
                *(uint2*)(hrow + c4) = cvt_h4(v);
            }
        }
#pragma unroll
        for (int off = 16; off > 0; off >>= 1)
            rs += __shfl_down_sync(0xffffffffu, rs, off);
        if (lane == 0) atomicAdd(&g_dv[r], rs);
    }
#pragma unroll
    for (int j = 0; j < 8; j++) {
        int c4 = (j * 256 + t) * 4;
        if (c4 < E_) {
#pragma unroll
            for (int q = 0; q < 4; q++) atomicAdd(&g_de[c4 + q], de_acc[j][q]);
        }
    }
}

// ---------------- Xs^T materialization (scaled, fp16, transposed) ----------
__global__ void __launch_bounds__(256) scale_x_t(const float* __restrict__ X) {
    __shared__ unsigned short sh[64 * 130];
    const int t = threadIdx.x;
    const int n0 = blockIdx.x * 128;
#pragma unroll
    for (int i = 0; i < 32; i++) {
        int idx = i * 256 + t;
        int nl = idx >> 6, f = idx & 63;
        int n = n0 + nl;
        float v = 0.0f;
        if (n < N_) v = X[(size_t)n * 64 + f] * rsqrtf(g_dv[n] + EPS);
        __half hv = __float2half_rn(v);
        sh[f * 130 + nl] = *(unsigned short*)&hv;
    }
    __syncthreads();
#pragma unroll
    for (int i = 0; i < 32; i++) {
        int idx = i * 256 + t;
        int f = idx >> 7, nl = idx & 127;
        int n = n0 + nl;
        if (n < NPAD) g_XsTf[(size_t)f * NPAD + n] = sh[f * 130 + nl];
    }
}

// ---------------- Yd^T: elementwise scale -> fp16 (f-major) ----------------
__global__ void __launch_bounds__(256) scale_y_t() {
    int i = blockIdx.x * blockDim.x + threadIdx.x;
    if (i < 64 * E_) {
        int e = i % E_;
        float v = g_YT[i] * (1.0f / (g_de[e] + EPS));
        __half hv = __float2half_rn(v);
        g_YdTf[i] = *(unsigned short*)&hv;
    }
}

// ============================================================================
// GEMM1: Y^T[64 f, E] += Xs^T[64 f, N] · H[N, E]  (fp16, 3-stage cp.async ring)
// 8 warps = 2 k-groups x (2 wf x 2 e-half). Warp tile 32f x 64e, 2 ks each.
// ============================================================================
__global__ void __launch_bounds__(256, 3)
gemm1_kernel() {
    extern __shared__ char smem[];
    const uint32_t sb = smem_u32(smem);
    const int t = threadIdx.x;
    const int lane = t & 31, w = t >> 5;
    const int e0 = blockIdx.x * 128;
    const int c_begin = blockIdx.y * CPS1;
    int c_end = c_begin + CPS1;
    if (c_end > NCH1) c_end = NCH1;
    const int nch = c_end - c_begin;

    const int kg = w >> 2;          // ks = kg*2 + {0,1}
    const int wq = w & 3;
    const int wf = wq & 1;          // 32-f slice
    const int half = wq >> 1;       // 64-e half

    const uint32_t amask = (uint32_t)((lane & 7) << 4);
    const uint32_t abase = (uint32_t)((wf * 32 + (lane & 15)) * 128);
    uint32_t kpa[2];
#pragma unroll
    for (int p = 0; p < 2; p++) {
        int ks = kg * 2 + p;
        kpa[p] = (uint32_t)(ks * 32 + (lane >> 4) * 16) ^ amask;
    }
    const int gq = lane >> 3, jj = lane & 7;
    const uint32_t m56 = (uint32_t)((jj << 4) & 96);
    const uint32_t bbase = (uint32_t)(half * 8192 + ((gq & 1) * 8 + jj) * 128 +
                                      (((gq >> 1) * 16) ^ ((jj << 4) & 16)));

    // Q (H16) cp.async loader: row qk, 4 chunks (2 halves x 2 segs)
    const int qk = t >> 2, qq = t & 3;
    uint32_t qdst[4];
    int qsoff[4];
    int qsz[4];
#pragma unroll
    for (int hh = 0; hh < 2; hh++)
#pragma unroll
        for (int j = 0; j < 2; j++) {
            int seg = qq * 2 + j;
            int idx = hh * 2 + j;
            qdst[idx] = (uint32_t)(G1_Q0 + hh * 8192) + SW128((uint32_t)(qk * 128 + seg * 16));
            qsoff[idx] = e0 + hh * 64 + seg * 8;
            qsz[idx] = (qsoff[idx] < E_) ? 16 : 0;
        }
    // P (XsT) cp.async loader
    const int fB = t >> 2, segB = t & 3;
    const uint32_t psts0 = SW128((uint32_t)(fB * 128 + segB * 16));
    const uint32_t psts1 = SW128((uint32_t)(fB * 128 + (segB + 4) * 16));
    const unsigned short* gXf = g_XsTf + (size_t)fB * NPAD + segB * 8;

    auto issue1 = [&](int cc, uint32_t dstb) {
        const int nb = cc * TK;
        const int n = nb + qk;
        const unsigned short* hrow = g_H16 + (size_t)n * E_;
        const bool nok = (n < N_);
#pragma unroll
        for (int i = 0; i < 4; i++)
            cp_async16z(dstb + qdst[i], hrow + qsoff[i], nok ? qsz[i] : 0);
        cp_async16(dstb + G1_P0 + psts0, gXf + nb);
        cp_async16(dstb + G1_P0 + psts1, gXf + nb + 32);
        CP_COMMIT();
    };

    float acc[2][8][4];
#pragma unroll
    for (int a = 0; a < 2; a++)
#pragma unroll
        for (int b = 0; b < 8; b++)
#pragma unroll
            for (int q = 0; q < 4; q++) acc[a][b][q] = 0.0f;

    // prologue: chunks 0,1 -> bufs 0,1
    issue1(c_begin, sb);
    if (nch > 1) issue1(c_begin + 1, sb + STAGE);
    else CP_COMMIT();

    int buf = 0;
    for (int c = 0; c < nch; c++) {
        if (c + 1 < nch) { CP_WAIT1(); } else { CP_WAIT0(); }
        __syncthreads();
        if (c + 2 < nch) {
            int pb = buf + 2;
            if (pb >= NSTG) pb -= NSTG;
            issue1(c_begin + c + 2, sb + pb * STAGE);
        }
        const uint32_t sbo = sb + buf * STAGE;

#pragma unroll
        for (int p = 0; p < 2; p++) {
            uint32_t ah[2][4];
#pragma unroll
            for (int mt = 0; mt < 2; mt++)
                LDMX4(ah[mt], sbo + G1_P0 + abase + (uint32_t)(mt * 2048) + kpa[p]);
            uint32_t bks = sbo + bbase + (uint32_t)((kg * 2 + p) * 2048);
#pragma unroll
            for (int prq = 0; prq < 2; prq++) {
                uint32_t bh[2][4];
#pragma unroll
                for (int pr2 = 0; pr2 < 2; pr2++)
                    LDMX4T(bh[pr2],
                           bks + (((uint32_t)((prq * 2 + pr2) * 32)) ^ m56) + G1_Q0);
#pragma unroll
                for (int mt = 0; mt < 2; mt++)
#pragma unroll
                    for (int pr2 = 0; pr2 < 2; pr2++)
#pragma unroll
                        for (int sub = 0; sub < 2; sub++)
                            mma_f16(acc[mt][(prq * 2 + pr2) * 2 + sub], ah[mt],
                                    bh[pr2][sub * 2], bh[pr2][sub * 2 + 1]);
            }
        }
        buf++;
        if (buf == NSTG) buf = 0;
    }

    // epilogue: atomic accumulate into g_YT [f][e] (both k-groups add)
#pragma unroll
    for (int mt = 0; mt < 2; mt++) {
        int f = wf * 32 + mt * 16 + (lane >> 2);
#pragma unroll
        for (int q = 0; q < 8; q++) {
            int e = e0 + half * 64 + q * 8 + (lane & 3) * 2;
            if (e < E_) {
                atomicAdd(&g_YT[(size_t)f * E_ + e], acc[mt][q][0]);
                atomicAdd(&g_YT[(size_t)f * E_ + e + 1], acc[mt][q][1]);
                atomicAdd(&g_YT[(size_t)(f + 8) * E_ + e], acc[mt][q][2]);
                atomicAdd(&g_YT[(size_t)(f + 8) * E_ + e + 1], acc[mt][q][3]);
            }
        }
    }
}

// ============================================================================
// GEMM2: Z[N,64] += D_v^{-1/2} · H[N,E] · Yd  (fp16, 3-stage cp.async ring)
// 8 warps = 2 k-groups x (2 wn x 2 wfc). Warp tile 64n x 32f, 2 ks each.
// ============================================================================
__global__ void __launch_bounds__(256, 3)
gemm2_kernel(float* __restrict__ Z) {
    extern __shared__ char smem[];
    const uint32_t sb = smem_u32(smem);
    const int t = threadIdx.x;
    const int lane = t & 31, w = t >> 5;
    const int n0 = blockIdx.x * 128;
    const int c_begin = blockIdx.y * CPS2;
    int c_end = c_begin + CPS2;
    if (c_end > NCH2) c_end = NCH2;
    const int nch = c_end - c_begin;

    const int kg = w >> 2;
    const int wq = w & 3;
    const int wn = wq >> 1;         // 64-n half
    const int wfc = wq & 1;         // 32-f slice

    const uint32_t amask = (uint32_t)((lane & 7) << 4);
    const uint32_t a2base = (uint32_t)((wn * 64 + (lane & 15)) * 128);
    uint32_t kpa[2];
#pragma unroll
    for (int p = 0; p < 2; p++) {
        int ks = kg * 2 + p;
        kpa[p] = (uint32_t)(ks * 32 + (lane >> 4) * 16) ^ amask;
    }
    const uint32_t b2base = (uint32_t)((wfc * 32 + (lane >> 4) * 8 + (lane & 7)) * 128);
    uint32_t kpb[2];
#pragma unroll
    for (int p = 0; p < 2; p++) {
        int ks = kg * 2 + p;
        kpb[p] = (uint32_t)(ks * 32 + ((lane >> 3) & 1) * 16) ^ amask;
    }

    // A (H16) cp.async loader: row ar, 4 chunks
    const int ar = t >> 1, aq = t & 1;
    uint32_t adst[4];
    int asoff[4];
#pragma unroll
    for (int j = 0; j < 4; j++) {
        int seg = aq * 4 + j;
        adst[j] = SW128((uint32_t)(ar * 128 + seg * 16));
        asoff[j] = seg * 8;
    }
    const bool a_nok = (n0 + ar < N_);
    const unsigned short* arow = g_H16 + (size_t)(n0 + ar) * E_;
    // B (YdT) cp.async loader
    const int fB = t >> 2, segB = t & 3;
    const uint32_t psts0 = SW128((uint32_t)(fB * 128 + segB * 16));
    const uint32_t psts1 = SW128((uint32_t)(fB * 128 + (segB + 4) * 16));
    const unsigned short* gYf = g_YdTf + (size_t)fB * E_ + segB * 8;

    auto issue2 = [&](int cc, uint32_t dstb) {
        const int kb = cc * TK;
#pragma unroll
        for (int j = 0; j < 4; j++)
            cp_async16z(dstb + G2_A0 + adst[j], arow + kb + asoff[j], a_nok ? 16 : 0);
        cp_async16(dstb + G2_B0 + psts0, gYf + kb);
        cp_async16(dstb + G2_B0 + psts1, gYf + kb + 32);
        CP_COMMIT();
    };

    float acc[4][4][4];
#pragma unroll
    for (int a = 0; a < 4; a++)
#pragma unroll
        for (int b = 0; b < 4; b++)
#pragma unroll
            for (int q = 0; q < 4; q++) acc[a][b][q] = 0.0f;

    // prologue: chunks 0,1 -> bufs 0,1
    issue2(c_begin, sb);
    if (nch > 1) issue2(c_begin + 1, sb + STAGE);
    else CP_COMMIT();

    int buf = 0;
    for (int c = 0; c < nch; c++) {
        if (c + 1 < nch) { CP_WAIT1(); } else { CP_WAIT0(); }
        __syncthreads();
        if (c + 2 < nch) {
            int pb = buf + 2;
            if (pb >= NSTG) pb -= NSTG;
            issue2(c_begin + c + 2, sb + pb * STAGE);
        }
        const uint32_t sbo = sb + buf * STAGE;

#pragma unroll
        for (int p = 0; p < 2; p++) {
            uint32_t bh[2][4];
#pragma unroll
            for (int nt = 0; nt < 2; nt++)
                LDMX4(bh[nt], sbo + G2_B0 + b2base + (uint32_t)(nt * 2048) + kpb[p]);
#pragma unroll
            for (int mg = 0; mg < 2; mg++) {
                uint32_t ah[2][4];
#pragma unroll
                for (int mi = 0; mi < 2; mi++)
                    LDMX4(ah[mi], sbo + G2_A0 + a2base +
                                  (uint32_t)((mg * 2 + mi) * 2048) + kpa[p]);
#pragma unroll
                for (int mi = 0; mi < 2; mi++)
#pragma unroll
                    for (int nt = 0; nt < 2; nt++)
#pragma unroll
                        for (int sub = 0; sub < 2; sub++)
                            mma_f16(acc[mg * 2 + mi][nt * 2 + sub], ah[mi],
                                    bh[nt][sub * 2], bh[nt][sub * 2 + 1]);
            }
        }
        buf++;
        if (buf == NSTG) buf = 0;
    }

    // epilogue: scale partials by rsqrt(d_v) and atomically accumulate
#pragma unroll
    for (int mt = 0; mt < 4; mt++) {
        int n_lo = n0 + wn * 64 + mt * 16 + (lane >> 2);
        int n_hi = n_lo + 8;
        float s_lo = (n_lo < N_) ? rsqrtf(g_dv[n_lo] + EPS) : 0.0f;
        float s_hi = (n_hi < N_) ? rsqrtf(g_dv[n_hi] + EPS) : 0.0f;
#pragma unroll
        for (int q = 0; q < 4; q++) {
            int f = wfc * 32 + q * 8 + (lane & 3) * 2;
            if (n_lo < N_) {
                atomicAdd(&Z[(size_t)n_lo * 64 + f], acc[mt][q][0] * s_lo);
                atomicAdd(&Z[(size_t)n_lo * 64 + f + 1], acc[mt][q][1] * s_lo);
            }
            if (n_hi < N_) {
                atomicAdd(&Z[(size_t)n_hi * 64 + f], acc[mt][q][2] * s_hi);
                atomicAdd(&Z[(size_t)n_hi * 64 + f + 1], acc[mt][q][3] * s_hi);
            }
        }
    }
}

// ---------------------------------------------------------------------------
extern "C" void kernel_launch(void* const* d_in, const int* in_sizes, int n_in,
                              void* d_out, int out_size) {
    const float* H = (const float*)d_in[0];  // [N_, E_] fp32
    const float* X = (const float*)d_in[1];  // [N_, F_] fp32
    float* Z = (float*)d_out;                // [N_, F_] fp32

    cudaFuncSetAttribute(gemm1_kernel, cudaFuncAttributeMaxDynamicSharedMemorySize, G_TOTAL);
    cudaFuncSetAttribute(gemm2_kernel, cudaFuncAttributeMaxDynamicSharedMemorySize, G_TOTAL);

    zero_scratch<<<(N_ * F_ + 255) / 256, 256>>>(Z);
    degrees_kernel<<<444, 256>>>(H);
    scale_x_t<<<(NPAD + 127) / 128, 256>>>(X);
    gemm1_kernel<<<dim3(ETILES1, SPLIT1), 256, G_TOTAL>>>();
    scale_y_t<<<(64 * E_ + 255) / 256, 256>>>();
    gemm2_kernel<<<dim3(NTILES2, SPLIT2), 256, G_TOTAL>>>(Z);
}

// round 16
// speedup vs baseline: 1.1293x; 1.1293x over previous
#include <cuda_runtime.h>
#include <cuda_bf16.h>
#include <cuda_fp16.h>
#include <cstdint>

#define N_ 20000
#define E_ 8000
#define F_ 64
#define EPS 1e-10f

#define NPAD 20032          // N_ padded to multiple of 64
#define TK 64               // K elements per chunk
#define NCH1 313            // NPAD/64
#define SPLIT1 7
#define CPS1 45             // ceil(313/7)
#define ETILES1 63          // ceil(E_/128)
#define NCH2 125            // E_/64
#define SPLIT2 3
#define CPS2 42             // ceil(125/3)
#define NTILES2 157         // ceil(N_/128)

// gemm1 per-stage: P 8K (XsT fp16) | Q 16K (H fp16, two 8K e-halves)
#define G1_P0 0
#define G1_Q0 8192
// gemm2 per-stage: A 16K (H fp16) | B 8K (YdT fp16)
#define G2_A0 0
#define G2_B0 16384
#define STAGE 24576
#define G_TOTAL (2 * STAGE)   // 49152 -> 3 CTAs/SM

// ---------------- scratch ----------------
__device__ float g_dv[N_];
__device__ float g_de[E_];
__device__ float g_YT[64 * E_];                      // Y^T [f][e]
__device__ __align__(16) unsigned short g_H16[(size_t)N_ * E_];  // H fp16
__device__ __align__(16) unsigned short g_XsTf[64 * NPAD];       // fp16
__device__ __align__(16) unsigned short g_YdTf[64 * E_];         // fp16 [f][e]

// ---------------- helpers ----------------
__device__ __forceinline__ uint32_t smem_u32(const void* p) {
    uint32_t a;
    asm("{ .reg .u64 tmp; cvta.to.shared.u64 tmp, %1; cvt.u32.u64 %0, tmp; }"
        : "=r"(a) : "l"(p));
    return a;
}
#define SW128(o) ((uint32_t)(o) ^ (((uint32_t)(o) >> 3) & 0x70))

__device__ __forceinline__ uint2 cvt_h4(float4 v) {
    __half2 a = __floats2half2_rn(v.x, v.y);
    __half2 b = __floats2half2_rn(v.z, v.w);
    return make_uint2(*(uint32_t*)&a, *(uint32_t*)&b);
}

#define LDMX4(r, addr) \
    asm volatile("ldmatrix.sync.aligned.m8n8.x4.shared.b16 {%0,%1,%2,%3}, [%4];" \
        : "=r"((r)[0]), "=r"((r)[1]), "=r"((r)[2]), "=r"((r)[3]) : "r"(addr))
#define LDMX4T(r, addr) \
    asm volatile("ldmatrix.sync.aligned.m8n8.x4.trans.shared.b16 {%0,%1,%2,%3}, [%4];" \
        : "=r"((r)[0]), "=r"((r)[1]), "=r"((r)[2]), "=r"((r)[3]) : "r"(addr))

__device__ __forceinline__ void mma_f16(float* c, const uint32_t* a,
                                        uint32_t b0, uint32_t b1) {
    asm volatile(
        "mma.sync.aligned.m16n8k16.row.col.f32.f16.f16.f32 "
        "{%0,%1,%2,%3}, {%4,%5,%6,%7}, {%8,%9}, {%0,%1,%2,%3};"
        : "+f"(c[0]), "+f"(c[1]), "+f"(c[2]), "+f"(c[3])
        : "r"(a[0]), "r"(a[1]), "r"(a[2]), "r"(a[3]), "r"(b0), "r"(b1));
}

__device__ __forceinline__ void cp_async16(uint32_t dst, const void* src) {
    asm volatile("cp.async.cg.shared.global [%0], [%1], 16;"
                 :: "r"(dst), "l"(src) : "memory");
}
__device__ __forceinline__ void cp_async16z(uint32_t dst, const void* src, int srcsz) {
    asm volatile("cp.async.cg.shared.global [%0], [%1], 16, %2;"
                 :: "r"(dst), "l"(src), "r"(srcsz) : "memory");
}
#define CP_COMMIT() asm volatile("cp.async.commit_group;" ::: "memory")
#define CP_WAIT0()  asm volatile("cp.async.wait_group 0;" ::: "memory")

// ---------------- zero scratch (incl. output + g_dv) ----------------
__global__ void zero_scratch(float* __restrict__ Z) {
    int i = blockIdx.x * blockDim.x + threadIdx.x;
    if (i < N_ * F_) Z[i] = 0.0f;
    if (i < 64 * E_) g_YT[i] = 0.0f;
    if (i < E_) g_de[i] = 0.0f;
    if (i < N_) g_dv[i] = 0.0f;
}

// ---------------- degrees + H16 conversion (one pass, no barriers) ----------
__global__ void __launch_bounds__(256) degrees_kernel(const float* __restrict__ H) {
    const int t = threadIdx.x;
    const int lane = t & 31;
    const int r0 = blockIdx.x * 46;
    const int r1 = (r0 + 46 < N_) ? r0 + 46 : N_;

    float de_acc[8][4];
#pragma unroll
    for (int j = 0; j < 8; j++)
#pragma unroll
        for (int q = 0; q < 4; q++) de_acc[j][q] = 0.0f;

    for (int r = r0; r < r1; r++) {
        const float* __restrict__ row = H + (size_t)r * E_;
        unsigned short* __restrict__ hrow = g_H16 + (size_t)r * E_;
        float rs = 0.0f;
#pragma unroll
        for (int j = 0; j < 8; j++) {
            int c4 = (j * 256 + t) * 4;
            if (c4 < E_) {
                float4 v = *(const float4*)(row + c4);
                rs += (v.x + v.y) + (v.z + v.w);
                de_acc[j][0] += v.x;
                de_acc[j][1] += v.y;
                de_acc[j][2] += v.z;
                de_acc[j][3] += v.w;
                *(uint2*)(hrow + c4) = cvt_h4(v);
            }
        }
#pragma unroll
        for (int off = 16; off > 0; off >>= 1)
            rs += __shfl_down_sync(0xffffffffu, rs, off);
        if (lane == 0) atomicAdd(&g_dv[r], rs);
    }
#pragma unroll
    for (int j = 0; j < 8; j++) {
        int c4 = (j * 256 + t) * 4;
        if (c4 < E_) {
#pragma unroll
            for (int q = 0; q < 4; q++) atomicAdd(&g_de[c4 + q], de_acc[j][q]);
        }
    }
}

// ---------------- Xs^T materialization (scaled, fp16, transposed) ----------
__global__ void __launch_bounds__(256) scale_x_t(const float* __restrict__ X) {
    __shared__ unsigned short sh[64 * 130];
    const int t = threadIdx.x;
    const int n0 = blockIdx.x * 128;
#pragma unroll
    for (int i = 0; i < 32; i++) {
        int idx = i * 256 + t;
        int nl = idx >> 6, f = idx & 63;
        int n = n0 + nl;
        float v = 0.0f;
        if (n < N_) v = X[(size_t)n * 64 + f] * rsqrtf(g_dv[n] + EPS);
        __half hv = __float2half_rn(v);
        sh[f * 130 + nl] = *(unsigned short*)&hv;
    }
    __syncthreads();
#pragma unroll
    for (int i = 0; i < 32; i++) {
        int idx = i * 256 + t;
        int f = idx >> 7, nl = idx & 127;
        int n = n0 + nl;
        if (n < NPAD) g_XsTf[(size_t)f * NPAD + n] = sh[f * 130 + nl];
    }
}

// ---------------- Yd^T: elementwise scale -> fp16 (f-major) ----------------
__global__ void __launch_bounds__(256) scale_y_t() {
    int i = blockIdx.x * blockDim.x + threadIdx.x;
    if (i < 64 * E_) {
        int e = i % E_;
        float v = g_YT[i] * (1.0f / (g_de[e] + EPS));
        __half hv = __float2half_rn(v);
        g_YdTf[i] = *(unsigned short*)&hv;
    }
}

// ============================================================================
// GEMM1: Y^T[64 f, E] += Xs^T[64 f, N] · H[N, E]  (fp16, 2-stage cp.async)
// 8 warps = 2 k-groups x (2 wf x 2 e-half). Warp tile 32f x 64e, 2 ks each.
// Loop body: issue(c+1) -> MMA(c) -> wait0 -> sync.
// ============================================================================
__global__ void __launch_bounds__(256, 3)
gemm1_kernel() {
    extern __shared__ char smem[];
    const uint32_t sb = smem_u32(smem);
    const int t = threadIdx.x;
    const int lane = t & 31, w = t >> 5;
    const int e0 = blockIdx.x * 128;
    const int c_begin = blockIdx.y * CPS1;
    int c_end = c_begin + CPS1;
    if (c_end > NCH1) c_end = NCH1;
    const int nch = c_end - c_begin;

    const int kg = w >> 2;          // ks = kg*2 + {0,1}
    const int wq = w & 3;
    const int wf = wq & 1;          // 32-f slice
    const int half = wq >> 1;       // 64-e half

    const uint32_t amask = (uint32_t)((lane & 7) << 4);
    const uint32_t abase = (uint32_t)((wf * 32 + (lane & 15)) * 128);
    uint32_t kpa[2];
#pragma unroll
    for (int p = 0; p < 2; p++) {
        int ks = kg * 2 + p;
        kpa[p] = (uint32_t)(ks * 32 + (lane >> 4) * 16) ^ amask;
    }
    const int gq = lane >> 3, jj = lane & 7;
    const uint32_t m56 = (uint32_t)((jj << 4) & 96);
    const uint32_t bbase = (uint32_t)(half * 8192 + ((gq & 1) * 8 + jj) * 128 +
                                      (((gq >> 1) * 16) ^ ((jj << 4) & 16)));

    // Q (H16) cp.async loader: row qk, 4 chunks (2 halves x 2 segs)
    const int qk = t >> 2, qq = t & 3;
    uint32_t qdst[4];
    int qsoff[4];
    int qsz[4];
#pragma unroll
    for (int hh = 0; hh < 2; hh++)
#pragma unroll
        for (int j = 0; j < 2; j++) {
            int seg = qq * 2 + j;
            int idx = hh * 2 + j;
            qdst[idx] = (uint32_t)(G1_Q0 + hh * 8192) + SW128((uint32_t)(qk * 128 + seg * 16));
            qsoff[idx] = e0 + hh * 64 + seg * 8;
            qsz[idx] = (qsoff[idx] < E_) ? 16 : 0;
        }
    // P (XsT) cp.async loader
    const int fB = t >> 2, segB = t & 3;
    const uint32_t psts0 = SW128((uint32_t)(fB * 128 + segB * 16));
    const uint32_t psts1 = SW128((uint32_t)(fB * 128 + (segB + 4) * 16));
    const unsigned short* gXf = g_XsTf + (size_t)fB * NPAD + segB * 8;

    auto issue1 = [&](int cc, uint32_t dstb) {
        const int nb = cc * TK;
        const int n = nb + qk;
        const unsigned short* hrow = g_H16 + (size_t)n * E_;
        const bool nok = (n < N_);
#pragma unroll
        for (int i = 0; i < 4; i++)
            cp_async16z(dstb + qdst[i], hrow + qsoff[i], nok ? qsz[i] : 0);
        cp_async16(dstb + G1_P0 + psts0, gXf + nb);
        cp_async16(dstb + G1_P0 + psts1, gXf + nb + 32);
        CP_COMMIT();
    };

    float acc[2][8][4];
#pragma unroll
    for (int a = 0; a < 2; a++)
#pragma unroll
        for (int b = 0; b < 8; b++)
#pragma unroll
            for (int q = 0; q < 4; q++) acc[a][b][q] = 0.0f;

    // prologue: chunk 0 -> buf 0
    issue1(c_begin, sb);
    CP_WAIT0();
    __syncthreads();

    for (int c = 0; c < nch; c++) {
        const int buf = c & 1;
        const uint32_t sbo = sb + buf * STAGE;
        const uint32_t nsb = sb + (buf ^ 1) * STAGE;
        const bool have = (c + 1 < nch);

        if (have) issue1(c_begin + c + 1, nsb);

        // ---- MMA passes ----
#pragma unroll
        for (int p = 0; p < 2; p++) {
            uint32_t ah[2][4];
#pragma unroll
            for (int mt = 0; mt < 2; mt++)
                LDMX4(ah[mt], sbo + G1_P0 + abase + (uint32_t)(mt * 2048) + kpa[p]);
            uint32_t bks = sbo + bbase + (uint32_t)((kg * 2 + p) * 2048);
#pragma unroll
            for (int prq = 0; prq < 2; prq++) {
                uint32_t bh[2][4];
#pragma unroll
                for (int pr2 = 0; pr2 < 2; pr2++)
                    LDMX4T(bh[pr2],
                           bks + (((uint32_t)((prq * 2 + pr2) * 32)) ^ m56) + G1_Q0);
#pragma unroll
                for (int mt = 0; mt < 2; mt++)
#pragma unroll
                    for (int pr2 = 0; pr2 < 2; pr2++)
#pragma unroll
                        for (int sub = 0; sub < 2; sub++)
                            mma_f16(acc[mt][(prq * 2 + pr2) * 2 + sub], ah[mt],
                                    bh[pr2][sub * 2], bh[pr2][sub * 2 + 1]);
            }
        }

        CP_WAIT0();
        __syncthreads();
    }

    // epilogue: atomic accumulate into g_YT [f][e] (both k-groups add)
#pragma unroll
    for (int mt = 0; mt < 2; mt++) {
        int f = wf * 32 + mt * 16 + (lane >> 2);
#pragma unroll
        for (int q = 0; q < 8; q++) {
            int e = e0 + half * 64 + q * 8 + (lane & 3) * 2;
            if (e < E_) {
                atomicAdd(&g_YT[(size_t)f * E_ + e], acc[mt][q][0]);
                atomicAdd(&g_YT[(size_t)f * E_ + e + 1], acc[mt][q][1]);
                atomicAdd(&g_YT[(size_t)(f + 8) * E_ + e], acc[mt][q][2]);
                atomicAdd(&g_YT[(size_t)(f + 8) * E_ + e + 1], acc[mt][q][3]);
            }
        }
    }
}

// ============================================================================
// GEMM2: Z[N,64] += D_v^{-1/2} · H[N,E] · Yd  (fp16, 2-stage cp.async)
// 8 warps = 2 k-groups x (2 wn x 2 wfc). Warp tile 64n x 32f, 2 ks each.
// ============================================================================
__global__ void __launch_bounds__(256, 3)
gemm2_kernel(float* __restrict__ Z) {
    extern __shared__ char smem[];
    const uint32_t sb = smem_u32(smem);
    const int t = threadIdx.x;
    const int lane = t & 31, w = t >> 5;
    const int n0 = blockIdx.x * 128;
    const int c_begin = blockIdx.y * CPS2;
    int c_end = c_begin + CPS2;
    if (c_end > NCH2) c_end = NCH2;
    const int nch = c_end - c_begin;

    const int kg = w >> 2;
    const int wq = w & 3;
    const int wn = wq >> 1;         // 64-n half
    const int wfc = wq & 1;         // 32-f slice

    const uint32_t amask = (uint32_t)((lane & 7) << 4);
    const uint32_t a2base = (uint32_t)((wn * 64 + (lane & 15)) * 128);
    uint32_t kpa[2];
#pragma unroll
    for (int p = 0; p < 2; p++) {
        int ks = kg * 2 + p;
        kpa[p] = (uint32_t)(ks * 32 + (lane >> 4) * 16) ^ amask;
    }
    const uint32_t b2base = (uint32_t)((wfc * 32 + (lane >> 4) * 8 + (lane & 7)) * 128);
    uint32_t kpb[2];
#pragma unroll
    for (int p = 0; p < 2; p++) {
        int ks = kg * 2 + p;
        kpb[p] = (uint32_t)(ks * 32 + ((lane >> 3) & 1) * 16) ^ amask;
    }

    // A (H16) cp.async loader: row ar, 4 chunks
    const int ar = t >> 1, aq = t & 1;
    uint32_t adst[4];
    int asoff[4];
#pragma unroll
    for (int j = 0; j < 4; j++) {
        int seg = aq * 4 + j;
        adst[j] = SW128((uint32_t)(ar * 128 + seg * 16));
        asoff[j] = seg * 8;
    }
    const bool a_nok = (n0 + ar < N_);
    const unsigned short* arow = g_H16 + (size_t)(n0 + ar) * E_;
    // B (YdT) cp.async loader
    const int fB = t >> 2, segB = t & 3;
    const uint32_t psts0 = SW128((uint32_t)(fB * 128 + segB * 16));
    const uint32_t psts1 = SW128((uint32_t)(fB * 128 + (segB + 4) * 16));
    const unsigned short* gYf = g_YdTf + (size_t)fB * E_ + segB * 8;

    auto issue2 = [&](int cc, uint32_t dstb) {
        const int kb = cc * TK;
#pragma unroll
        for (int j = 0; j < 4; j++)
            cp_async16z(dstb + G2_A0 + adst[j], arow + kb + asoff[j], a_nok ? 16 : 0);
        cp_async16(dstb + G2_B0 + psts0, gYf + kb);
        cp_async16(dstb + G2_B0 + psts1, gYf + kb + 32);
        CP_COMMIT();
    };

    float acc[4][4][4];
#pragma unroll
    for (int a = 0; a < 4; a++)
#pragma unroll
        for (int b = 0; b < 4; b++)
#pragma unroll
            for (int q = 0; q < 4; q++) acc[a][b][q] = 0.0f;

    // prologue: chunk 0 -> buf 0
    issue2(c_begin, sb);
    CP_WAIT0();
    __syncthreads();

    for (int c = 0; c < nch; c++) {
        const int buf = c & 1;
        const uint32_t sbo = sb + buf * STAGE;
        const uint32_t nsb = sb + (buf ^ 1) * STAGE;
        const bool have = (c + 1 < nch);

        if (have) issue2(c_begin + c + 1, nsb);

        // ---- MMA passes ----
#pragma unroll
        for (int p = 0; p < 2; p++) {
            uint32_t bh[2][4];
#pragma unroll
            for (int nt = 0; nt < 2; nt++)
                LDMX4(bh[nt], sbo + G2_B0 + b2base + (uint32_t)(nt * 2048) + kpb[p]);
#pragma unroll
            for (int mg = 0; mg < 2; mg++) {
                uint32_t ah[2][4];
#pragma unroll
                for (int mi = 0; mi < 2; mi++)
                    LDMX4(ah[mi], sbo + G2_A0 + a2base +
                                  (uint32_t)((mg * 2 + mi) * 2048) + kpa[p]);
#pragma unroll
                for (int mi = 0; mi < 2; mi++)
#pragma unroll
                    for (int nt = 0; nt < 2; nt++)
#pragma unroll
                        for (int sub = 0; sub < 2; sub++)
                            mma_f16(acc[mg * 2 + mi][nt * 2 + sub], ah[mi],
                                    bh[nt][sub * 2], bh[nt][sub * 2 + 1]);
            }
        }

        CP_WAIT0();
        __syncthreads();
    }

    // epilogue: scale partials by rsqrt(d_v) and atomically accumulate
#pragma unroll
    for (int mt = 0; mt < 4; mt++) {
        int n_lo = n0 + wn * 64 + mt * 16 + (lane >> 2);
        int n_hi = n_lo + 8;
        float s_lo = (n_lo < N_) ? rsqrtf(g_dv[n_lo] + EPS) : 0.0f;
        float s_hi = (n_hi < N_) ? rsqrtf(g_dv[n_hi] + EPS) : 0.0f;
#pragma unroll
        for (int q = 0; q < 4; q++) {
            int f = wfc * 32 + q * 8 + (lane & 3) * 2;
            if (n_lo < N_) {
                atomicAdd(&Z[(size_t)n_lo * 64 + f], acc[mt][q][0] * s_lo);
                atomicAdd(&Z[(size_t)n_lo * 64 + f + 1], acc[mt][q][1] * s_lo);
            }
            if (n_hi < N_) {
                atomicAdd(&Z[(size_t)n_hi * 64 + f], acc[mt][q][2] * s_hi);
                atomicAdd(&Z[(size_t)n_hi * 64 + f + 1], acc[mt][q][3] * s_hi);
            }
        }
    }
}

// ---------------------------------------------------------------------------
extern "C" void kernel_launch(void* const* d_in, const int* in_sizes, int n_in,
                              void* d_out, int out_size) {
    const float* H = (const float*)d_in[0];  // [N_, E_] fp32
    const float* X = (const float*)d_in[1];  // [N_, F_] fp32
    float* Z = (float*)d_out;                // [N_, F_] fp32

    cudaFuncSetAttribute(gemm1_kernel, cudaFuncAttributeMaxDynamicSharedMemorySize, G_TOTAL);
    cudaFuncSetAttribute(gemm2_kernel, cudaFuncAttributeMaxDynamicSharedMemorySize, G_TOTAL);

    zero_scratch<<<(N_ * F_ + 255) / 256, 256>>>(Z);
    degrees_kernel<<<444, 256>>>(H);
    scale_x_t<<<(NPAD + 127) / 128, 256>>>(X);
    gemm1_kernel<<<dim3(ETILES1, SPLIT1), 256, G_TOTAL>>>();
    scale_y_t<<<(64 * E_ + 255) / 256, 256>>>();
    gemm2_kernel<<<dim3(NTILES2, SPLIT2), 256, G_TOTAL>>>(Z);
}

// round 17
// speedup vs baseline: 1.1626x; 1.0295x over previous
#include <cuda_runtime.h>
#include <cuda_bf16.h>
#include <cuda_fp16.h>
#include <cstdint>

#define N_ 20000
#define E_ 8000
#define F_ 64
#define EPS 1e-10f

#define NPAD 20032          // N_ padded to multiple of 64
#define TK 64               // K elements per chunk
#define NCH1 313            // NPAD/64
#define SPLIT1 7
#define CPS1 45             // ceil(313/7)
#define ETILES1 63          // ceil(E_/128)
#define NCH2 125            // E_/64
#define NTILES2 157         // ceil(N_/128)
#define G2_CTAS 444         // 148 SMs x 3 CTAs, exactly one wave
#define G2_WTOT (NTILES2 * NCH2)            // 19625
#define G2_WLO (G2_WTOT / G2_CTAS)          // 44
#define G2_WREM (G2_WTOT % G2_CTAS)         // 89

// gemm1 per-stage: P 8K (XsT fp16) | Q 16K (H fp16, two 8K e-halves)
#define G1_P0 0
#define G1_Q0 8192
// gemm2 per-stage: A 16K (H fp16) | B 8K (YdT fp16)
#define G2_A0 0
#define G2_B0 16384
#define STAGE 24576
#define G_TOTAL (2 * STAGE)   // 49152 -> 3 CTAs/SM

// ---------------- scratch ----------------
__device__ float g_dv[N_];
__device__ float g_de[E_];
__device__ float g_YT[64 * E_];                      // Y^T [f][e]
__device__ __align__(16) unsigned short g_H16[(size_t)N_ * E_];  // H fp16
__device__ __align__(16) unsigned short g_XsTf[64 * NPAD];       // fp16
__device__ __align__(16) unsigned short g_YdTf[64 * E_];         // fp16 [f][e]

// ---------------- helpers ----------------
__device__ __forceinline__ uint32_t smem_u32(const void* p) {
    uint32_t a;
    asm("{ .reg .u64 tmp; cvta.to.shared.u64 tmp, %1; cvt.u32.u64 %0, tmp; }"
        : "=r"(a) : "l"(p));
    return a;
}
#define SW128(o) ((uint32_t)(o) ^ (((uint32_t)(o) >> 3) & 0x70))

__device__ __forceinline__ uint2 cvt_h4(float4 v) {
    __half2 a = __floats2half2_rn(v.x, v.y);
    __half2 b = __floats2half2_rn(v.z, v.w);
    return make_uint2(*(uint32_t*)&a, *(uint32_t*)&b);
}

#define LDMX4(r, addr) \
    asm volatile("ldmatrix.sync.aligned.m8n8.x4.shared.b16 {%0,%1,%2,%3}, [%4];" \
        : "=r"((r)[0]), "=r"((r)[1]), "=r"((r)[2]), "=r"((r)[3]) : "r"(addr))
#define LDMX4T(r, addr) \
    asm volatile("ldmatrix.sync.aligned.m8n8.x4.trans.shared.b16 {%0,%1,%2,%3}, [%4];" \
        : "=r"((r)[0]), "=r"((r)[1]), "=r"((r)[2]), "=r"((r)[3]) : "r"(addr))

__device__ __forceinline__ void mma_f16(float* c, const uint32_t* a,
                                        uint32_t b0, uint32_t b1) {
    asm volatile(
        "mma.sync.aligned.m16n8k16.row.col.f32.f16.f16.f32 "
        "{%0,%1,%2,%3}, {%4,%5,%6,%7}, {%8,%9}, {%0,%1,%2,%3};"
        : "+f"(c[0]), "+f"(c[1]), "+f"(c[2]), "+f"(c[3])
        : "r"(a[0]), "r"(a[1]), "r"(a[2]), "r"(a[3]), "r"(b0), "r"(b1));
}

__device__ __forceinline__ void cp_async16(uint32_t dst, const void* src) {
    asm volatile("cp.async.cg.shared.global [%0], [%1], 16;"
                 :: "r"(dst), "l"(src) : "memory");
}
__device__ __forceinline__ void cp_async16z(uint32_t dst, const void* src, int srcsz) {
    asm volatile("cp.async.cg.shared.global [%0], [%1], 16, %2;"
                 :: "r"(dst), "l"(src), "r"(srcsz) : "memory");
}
#define CP_COMMIT() asm volatile("cp.async.commit_group;" ::: "memory")
#define CP_WAIT0()  asm volatile("cp.async.wait_group 0;" ::: "memory")

// ---------------- zero scratch (incl. output + g_dv) ----------------
__global__ void zero_scratch(float* __restrict__ Z) {
    int i = blockIdx.x * blockDim.x + threadIdx.x;
    if (i < N_ * F_) Z[i] = 0.0f;
    if (i < 64 * E_) g_YT[i] = 0.0f;
    if (i < E_) g_de[i] = 0.0f;
    if (i < N_) g_dv[i] = 0.0f;
}

// ---------------- degrees + H16 conversion (one pass, no barriers) ----------
__global__ void __launch_bounds__(256) degrees_kernel(const float* __restrict__ H) {
    const int t = threadIdx.x;
    const int lane = t & 31;
    const int r0 = blockIdx.x * 46;
    const int r1 = (r0 + 46 < N_) ? r0 + 46 : N_;

    float de_acc[8][4];
#pragma unroll
    for (int j = 0; j < 8; j++)
#pragma unroll
        for (int q = 0; q < 4; q++) de_acc[j][q] = 0.0f;

    for (int r = r0; r < r1; r++) {
        const float* __restrict__ row = H + (size_t)r * E_;
        unsigned short* __restrict__ hrow = g_H16 + (size_t)r * E_;
        float rs = 0.0f;
#pragma unroll
        for (int j = 0; j < 8; j++) {
            int c4 = (j * 256 + t) * 4;
            if (c4 < E_) {
                float4 v = *(const float4*)(row + c4);
                rs += (v.x + v.y) + (v.z + v.w);
                de_acc[j][0] += v.x;
                de_acc[j][1] += v.y;
                de_acc[j][2] += v.z;
                de_acc[j][3] += v.w;
                *(uint2*)(hrow + c4) = cvt_h4(v);
            }
        }
#pragma unroll
        for (int off = 16; off > 0; off >>= 1)
            rs += __shfl_down_sync(0xffffffffu, rs, off);
        if (lane == 0) atomicAdd(&g_dv[r], rs);
    }
#pragma unroll
    for (int j = 0; j < 8; j++) {
        int c4 = (j * 256 + t) * 4;
        if (c4 < E_) {
#pragma unroll
            for (int q = 0; q < 4; q++) atomicAdd(&g_de[c4 + q], de_acc[j][q]);
        }
    }
}

// ---------------- Xs^T materialization (scaled, fp16, transposed) ----------
__global__ void __launch_bounds__(256) scale_x_t(const float* __restrict__ X) {
    __shared__ unsigned short sh[64 * 130];
    const int t = threadIdx.x;
    const int n0 = blockIdx.x * 128;
#pragma unroll
    for (int i = 0; i < 32; i++) {
        int idx = i * 256 + t;
        int nl = idx >> 6, f = idx & 63;
        int n = n0 + nl;
        float v = 0.0f;
        if (n < N_) v = X[(size_t)n * 64 + f] * rsqrtf(g_dv[n] + EPS);
        __half hv = __float2half_rn(v);
        sh[f * 130 + nl] = *(unsigned short*)&hv;
    }
    __syncthreads();
#pragma unroll
    for (int i = 0; i < 32; i++) {
        int idx = i * 256 + t;
        int f = idx >> 7, nl = idx & 127;
        int n = n0 + nl;
        if (n < NPAD) g_XsTf[(size_t)f * NPAD + n] = sh[f * 130 + nl];
    }
}

// ---------------- Yd^T: elementwise scale -> fp16 (f-major) ----------------
__global__ void __launch_bounds__(256) scale_y_t() {
    int i = blockIdx.x * blockDim.x + threadIdx.x;
    if (i < 64 * E_) {
        int e = i % E_;
        float v = g_YT[i] * (1.0f / (g_de[e] + EPS));
        __half hv = __float2half_rn(v);
        g_YdTf[i] = *(unsigned short*)&hv;
    }
}

// ============================================================================
// GEMM1: Y^T[64 f, E] += Xs^T[64 f, N] · H[N, E]  (fp16, 2-stage cp.async)
// 8 warps = 2 k-groups x (2 wf x 2 e-half). Warp tile 32f x 64e, 2 ks each.
// ============================================================================
__global__ void __launch_bounds__(256, 3)
gemm1_kernel() {
    extern __shared__ char smem[];
    const uint32_t sb = smem_u32(smem);
    const int t = threadIdx.x;
    const int lane = t & 31, w = t >> 5;
    const int e0 = blockIdx.x * 128;
    const int c_begin = blockIdx.y * CPS1;
    int c_end = c_begin + CPS1;
    if (c_end > NCH1) c_end = NCH1;
    const int nch = c_end - c_begin;

    const int kg = w >> 2;          // ks = kg*2 + {0,1}
    const int wq = w & 3;
    const int wf = wq & 1;          // 32-f slice
    const int half = wq >> 1;       // 64-e half

    const uint32_t amask = (uint32_t)((lane & 7) << 4);
    const uint32_t abase = (uint32_t)((wf * 32 + (lane & 15)) * 128);
    uint32_t kpa[2];
#pragma unroll
    for (int p = 0; p < 2; p++) {
        int ks = kg * 2 + p;
        kpa[p] = (uint32_t)(ks * 32 + (lane >> 4) * 16) ^ amask;
    }
    const int gq = lane >> 3, jj = lane & 7;
    const uint32_t m56 = (uint32_t)((jj << 4) & 96);
    const uint32_t bbase = (uint32_t)(half * 8192 + ((gq & 1) * 8 + jj) * 128 +
                                      (((gq >> 1) * 16) ^ ((jj << 4) & 16)));

    // Q (H16) cp.async loader: row qk, 4 chunks (2 halves x 2 segs)
    const int qk = t >> 2, qq = t & 3;
    uint32_t qdst[4];
    int qsoff[4];
    int qsz[4];
#pragma unroll
    for (int hh = 0; hh < 2; hh++)
#pragma unroll
        for (int j = 0; j < 2; j++) {
            int seg = qq * 2 + j;
            int idx = hh * 2 + j;
            qdst[idx] = (uint32_t)(G1_Q0 + hh * 8192) + SW128((uint32_t)(qk * 128 + seg * 16));
            qsoff[idx] = e0 + hh * 64 + seg * 8;
            qsz[idx] = (qsoff[idx] < E_) ? 16 : 0;
        }
    // P (XsT) cp.async loader
    const int fB = t >> 2, segB = t & 3;
    const uint32_t psts0 = SW128((uint32_t)(fB * 128 + segB * 16));
    const uint32_t psts1 = SW128((uint32_t)(fB * 128 + (segB + 4) * 16));
    const unsigned short* gXf = g_XsTf + (size_t)fB * NPAD + segB * 8;

    auto issue1 = [&](int cc, uint32_t dstb) {
        const int nb = cc * TK;
        const int n = nb + qk;
        const unsigned short* hrow = g_H16 + (size_t)n * E_;
        const bool nok = (n < N_);
#pragma unroll
        for (int i = 0; i < 4; i++)
            cp_async16z(dstb + qdst[i], hrow + qsoff[i], nok ? qsz[i] : 0);
        cp_async16(dstb + G1_P0 + psts0, gXf + nb);
        cp_async16(dstb + G1_P0 + psts1, gXf + nb + 32);
        CP_COMMIT();
    };

    float acc[2][8][4];
#pragma unroll
    for (int a = 0; a < 2; a++)
#pragma unroll
        for (int b = 0; b < 8; b++)
#pragma unroll
            for (int q = 0; q < 4; q++) acc[a][b][q] = 0.0f;

    // prologue: chunk 0 -> buf 0
    issue1(c_begin, sb);
    CP_WAIT0();
    __syncthreads();

    for (int c = 0; c < nch; c++) {
        const int buf = c & 1;
        const uint32_t sbo = sb + buf * STAGE;
        const uint32_t nsb = sb + (buf ^ 1) * STAGE;
        const bool have = (c + 1 < nch);

        if (have) issue1(c_begin + c + 1, nsb);

        // ---- MMA passes ----
#pragma unroll
        for (int p = 0; p < 2; p++) {
            uint32_t ah[2][4];
#pragma unroll
            for (int mt = 0; mt < 2; mt++)
                LDMX4(ah[mt], sbo + G1_P0 + abase + (uint32_t)(mt * 2048) + kpa[p]);
            uint32_t bks = sbo + bbase + (uint32_t)((kg * 2 + p) * 2048);
#pragma unroll
            for (int prq = 0; prq < 2; prq++) {
                uint32_t bh[2][4];
#pragma unroll
                for (int pr2 = 0; pr2 < 2; pr2++)
                    LDMX4T(bh[pr2],
                           bks + (((uint32_t)((prq * 2 + pr2) * 32)) ^ m56) + G1_Q0);
#pragma unroll
                for (int mt = 0; mt < 2; mt++)
#pragma unroll
                    for (int pr2 = 0; pr2 < 2; pr2++)
#pragma unroll
                        for (int sub = 0; sub < 2; sub++)
                            mma_f16(acc[mt][(prq * 2 + pr2) * 2 + sub], ah[mt],
                                    bh[pr2][sub * 2], bh[pr2][sub * 2 + 1]);
            }
        }

        CP_WAIT0();
        __syncthreads();
    }

    // epilogue: atomic accumulate into g_YT [f][e] (both k-groups add)
#pragma unroll
    for (int mt = 0; mt < 2; mt++) {
        int f = wf * 32 + mt * 16 + (lane >> 2);
#pragma unroll
        for (int q = 0; q < 8; q++) {
            int e = e0 + half * 64 + q * 8 + (lane & 3) * 2;
            if (e < E_) {
                atomicAdd(&g_YT[(size_t)f * E_ + e], acc[mt][q][0]);
                atomicAdd(&g_YT[(size_t)f * E_ + e + 1], acc[mt][q][1]);
                atomicAdd(&g_YT[(size_t)(f + 8) * E_ + e], acc[mt][q][2]);
                atomicAdd(&g_YT[(size_t)(f + 8) * E_ + e + 1], acc[mt][q][3]);
            }
        }
    }
}

// ============================================================================
// GEMM2: Z[N,64] += D_v^{-1/2} · H[N,E] · Yd  (fp16, 2-stage cp.async,
// persistent balanced: 444 CTAs over 157x125 chunk-items, <=2 tile segments)
// 8 warps = 2 k-groups x (2 wn x 2 wfc). Warp tile 64n x 32f, 2 ks each.
// ============================================================================
__global__ void __launch_bounds__(256, 3)
gemm2_kernel(float* __restrict__ Z) {
    extern __shared__ char smem[];
    const uint32_t sb = smem_u32(smem);
    const int t = threadIdx.x;
    const int lane = t & 31, w = t >> 5;
    const int g = blockIdx.x;

    const int kg = w >> 2;
    const int wq = w & 3;
    const int wn = wq >> 1;         // 64-n half
    const int wfc = wq & 1;         // 32-f slice

    const uint32_t amask = (uint32_t)((lane & 7) << 4);
    const uint32_t a2base = (uint32_t)((wn * 64 + (lane & 15)) * 128);
    uint32_t kpa[2];
#pragma unroll
    for (int p = 0; p < 2; p++) {
        int ks = kg * 2 + p;
        kpa[p] = (uint32_t)(ks * 32 + (lane >> 4) * 16) ^ amask;
    }
    const uint32_t b2base = (uint32_t)((wfc * 32 + (lane >> 4) * 8 + (lane & 7)) * 128);
    uint32_t kpb[2];
#pragma unroll
    for (int p = 0; p < 2; p++) {
        int ks = kg * 2 + p;
        kpb[p] = (uint32_t)(ks * 32 + ((lane >> 3) & 1) * 16) ^ amask;
    }

    // A (H16) cp.async loader: row ar, 4 chunks
    const int ar = t >> 1, aq = t & 1;
    uint32_t adst[4];
    int asoff[4];
#pragma unroll
    for (int j = 0; j < 4; j++) {
        int seg = aq * 4 + j;
        adst[j] = SW128((uint32_t)(ar * 128 + seg * 16));
        asoff[j] = seg * 8;
    }
    // B (YdT) cp.async loader
    const int fB = t >> 2, segB = t & 3;
    const uint32_t psts0 = SW128((uint32_t)(fB * 128 + segB * 16));
    const uint32_t psts1 = SW128((uint32_t)(fB * 128 + (segB + 4) * 16));
    const unsigned short* gYf = g_YdTf + (size_t)fB * E_ + segB * 8;

    // persistent work range
    int item = g * G2_WLO + (g < G2_WREM ? g : G2_WREM);
    int remaining = G2_WLO + (g < G2_WREM ? 1 : 0);

    // per-segment state
    const unsigned short* arow = nullptr;
    bool a_nok = false;

    auto issue2 = [&](int cc, uint32_t dstb) {
        const int kb = cc * TK;
#pragma unroll
        for (int j = 0; j < 4; j++)
            cp_async16z(dstb + G2_A0 + adst[j], arow + kb + asoff[j], a_nok ? 16 : 0);
        cp_async16(dstb + G2_B0 + psts0, gYf + kb);
        cp_async16(dstb + G2_B0 + psts1, gYf + kb + 32);
        CP_COMMIT();
    };

    float acc[4][4][4];

    while (remaining > 0) {
        const int tile = item / NCH2;
        const int c0 = item % NCH2;
        int L = NCH2 - c0;
        if (L > remaining) L = remaining;
        const int n0 = tile * 128;
        arow = g_H16 + (size_t)(n0 + ar) * E_;
        a_nok = (n0 + ar < N_);

#pragma unroll
        for (int a = 0; a < 4; a++)
#pragma unroll
            for (int b = 0; b < 4; b++)
#pragma unroll
                for (int q = 0; q < 4; q++) acc[a][b][q] = 0.0f;

        // prologue: first chunk -> buf 0
        issue2(c0, sb);
        CP_WAIT0();
        __syncthreads();

        for (int c = 0; c < L; c++) {
            const int buf = c & 1;
            const uint32_t sbo = sb + buf * STAGE;
            const uint32_t nsb = sb + (buf ^ 1) * STAGE;
            const bool have = (c + 1 < L);

            if (have) issue2(c0 + c + 1, nsb);

#pragma unroll
            for (int p = 0; p < 2; p++) {
                uint32_t bh[2][4];
#pragma unroll
                for (int nt = 0; nt < 2; nt++)
                    LDMX4(bh[nt], sbo + G2_B0 + b2base + (uint32_t)(nt * 2048) + kpb[p]);
#pragma unroll
                for (int mg = 0; mg < 2; mg++) {
                    uint32_t ah[2][4];
#pragma unroll
                    for (int mi = 0; mi < 2; mi++)
                        LDMX4(ah[mi], sbo + G2_A0 + a2base +
                                      (uint32_t)((mg * 2 + mi) * 2048) + kpa[p]);
#pragma unroll
                    for (int mi = 0; mi < 2; mi++)
#pragma unroll
                        for (int nt = 0; nt < 2; nt++)
#pragma unroll
                            for (int sub = 0; sub < 2; sub++)
                                mma_f16(acc[mg * 2 + mi][nt * 2 + sub], ah[mi],
                                        bh[nt][sub * 2], bh[nt][sub * 2 + 1]);
                }
            }

            CP_WAIT0();
            __syncthreads();
        }

        // epilogue for this tile: scale by rsqrt(d_v), atomic accumulate
#pragma unroll
        for (int mt = 0; mt < 4; mt++) {
            int n_lo = n0 + wn * 64 + mt * 16 + (lane >> 2);
            int n_hi = n_lo + 8;
            float s_lo = (n_lo < N_) ? rsqrtf(g_dv[n_lo] + EPS) : 0.0f;
            float s_hi = (n_hi < N_) ? rsqrtf(g_dv[n_hi] + EPS) : 0.0f;
#pragma unroll
            for (int q = 0; q < 4; q++) {
                int f = wfc * 32 + q * 8 + (lane & 3) * 2;
                if (n_lo < N_) {
                    atomicAdd(&Z[(size_t)n_lo * 64 + f], acc[mt][q][0] * s_lo);
                    atomicAdd(&Z[(size_t)n_lo * 64 + f + 1], acc[mt][q][1] * s_lo);
                }
                if (n_hi < N_) {
                    atomicAdd(&Z[(size_t)n_hi * 64 + f], acc[mt][q][2] * s_hi);
                    atomicAdd(&Z[(size_t)n_hi * 64 + f + 1], acc[mt][q][3] * s_hi);
                }
            }
        }

        item += L;
        remaining -= L;
    }
}

// ---------------------------------------------------------------------------
extern "C" void kernel_launch(void* const* d_in, const int* in_sizes, int n_in,
                              void* d_out, int out_size) {
    const float* H = (const float*)d_in[0];  // [N_, E_] fp32
    const float* X = (const float*)d_in[1];  // [N_, F_] fp32
    float* Z = (float*)d_out;                // [N_, F_] fp32

    cudaFuncSetAttribute(gemm1_kernel, cudaFuncAttributeMaxDynamicSharedMemorySize, G_TOTAL);
    cudaFuncSetAttribute(gemm2_kernel, cudaFuncAttributeMaxDynamicSharedMemorySize, G_TOTAL);

    zero_scratch<<<(N_ * F_ + 255) / 256, 256>>>(Z);
    degrees_kernel<<<444, 256>>>(H);
    scale_x_t<<<(NPAD + 127) / 128, 256>>>(X);
    gemm1_kernel<<<dim3(ETILES1, SPLIT1), 256, G_TOTAL>>>();
    scale_y_t<<<(64 * E_ + 255) / 256, 256>>>();
    gemm2_kernel<<<G2_CTAS, 256, G_TOTAL>>>(Z);
}